// round 5
// baseline (speedup 1.0000x reference)
#include <cuda_runtime.h>

#define BN 8
#define CN 128
#define HN 128
#define WN 128
#define KWN 9
#define PWN 4
#define GSL 16          // CTAs per batch (co-slices)
#define COS 8           // output channels per CTA
#define NTH 256
#define ROWP 132        // padded smem row pitch (floats) -> conflict-free
#define BSTR (HN*WN*CN) // per-batch stride in floats

// Scratch state tensor in NHWC, processed in-place by all 4 scans.
__device__ float g_Y[(size_t)BN * HN * WN * CN];
// Per-phase, per-batch, per-step completion counters.
__device__ int g_cnt[4 * BN * HN];

__global__ void zero_cnt_k() {
    int i = blockIdx.x * blockDim.x + threadIdx.x;
    if (i < 4 * BN * HN) g_cnt[i] = 0;
}

// Generic per-batch tiled transpose: in is (B, R, Cc), out is (B, Cc, R).
__global__ void transpose_k(const float* __restrict__ in, float* __restrict__ out,
                            int R, int Cc) {
    __shared__ float tile[32][33];
    int b = blockIdx.z;
    size_t base = (size_t)b * R * Cc;
    int j0 = blockIdx.x << 5, i0 = blockIdx.y << 5;
    int tx = threadIdx.x, ty = threadIdx.y;
#pragma unroll
    for (int k = 0; k < 32; k += 8)
        tile[ty + k][tx] = in[base + (size_t)(i0 + ty + k) * Cc + (j0 + tx)];
    __syncthreads();
#pragma unroll
    for (int k = 0; k < 32; k += 8)
        out[base + (size_t)(j0 + ty + k) * R + (i0 + tx)] = tile[tx][ty + k];
}

// One directional scan, persistent. Grid (GSL, BN), 256 threads.
// Row element address: b*BSTR + r*RS + t*TS + c  (r = scan index, t = conv axis pos).
// Recurrence: Y[tgt] = Y[tgt] + relu(conv_KW9(Y[src]))   (in-place).
__global__ void __launch_bounds__(NTH, 1)
scan_k(const float* __restrict__ kern, int phase, int RS, int TS, int rev) {
    extern __shared__ float sm[];
    float* ws = sm;                  // [KWN][CN][COS] weight slice: 9216 floats
    float* ps = sm + KWN * CN * COS; // [WN][ROWP] staged prev row

    const int tid = threadIdx.x;
    const int b = blockIdx.y, g = blockIdx.x;
    const int co0 = g * COS;

    // Load this CTA's weight slice once (resident whole kernel).
    for (int i = tid; i < KWN * CN * COS; i += NTH) {
        int kwi = i / (CN * COS);
        int r = i - kwi * (CN * COS);
        int ci = r >> 3, j = r & 7;
        ws[i] = kern[(kwi * CN + ci) * CN + co0 + j];
    }
    __syncthreads();

    const int lane = tid & 31, wq = tid >> 5;
    const int w = (wq << 4) + (lane & 15);  // conv-axis position this lane owns
    const int ch = lane >> 4;               // which half of the 8 co's
    const int c0 = co0 + (ch << 2);
    const size_t baseb = (size_t)b * BSTR;
    int* cnt = g_cnt + (phase * BN + b) * HN;

    for (int s = 1; s < HN; s++) {
        const int tgt = rev ? (HN - 1 - s) : s;
        const int src = rev ? (tgt + 1) : (tgt - 1);

        // Wait until all GSL CTAs of this batch finished step s-1.
        if (s > 1) {
            if (tid == 0) {
                volatile int* p = cnt + (s - 1);
                while (*p < GSL) __nanosleep(64);
            }
            __syncthreads();
        }

        // Stage src row (128 positions x 128 channels) into padded smem.
        {
            const size_t rb = baseb + (size_t)src * RS;
            for (int i = tid; i < WN * (CN / 4); i += NTH) {
                int t = i >> 5;
                int cq = (i & 31) << 2;
                float4 v = __ldcg((const float4*)(g_Y + rb + (size_t)t * TS + cq));
                *(float4*)(ps + t * ROWP + cq) = v;
            }
        }
        __syncthreads();

        // conv: acc[j] = sum_{kk,ci} prev[w+kk-4, ci] * K[kk, ci, c0+j]
        float4 acc = make_float4(0.f, 0.f, 0.f, 0.f);
#pragma unroll
        for (int kk = 0; kk < KWN; kk++) {
            const int wr = w + kk - PWN;
            if ((unsigned)wr < (unsigned)WN) {
                const float* pr = ps + wr * ROWP;
                const float* wrp = ws + kk * (CN * COS) + (ch << 2);
#pragma unroll 8
                for (int ci = 0; ci < CN; ci += 4) {
                    float4 a  = *(const float4*)(pr + ci);
                    float4 w0 = *(const float4*)(wrp + (ci    ) * COS);
                    float4 w1 = *(const float4*)(wrp + (ci + 1) * COS);
                    float4 w2 = *(const float4*)(wrp + (ci + 2) * COS);
                    float4 w3 = *(const float4*)(wrp + (ci + 3) * COS);
                    acc.x = fmaf(a.x, w0.x, acc.x);
                    acc.y = fmaf(a.x, w0.y, acc.y);
                    acc.z = fmaf(a.x, w0.z, acc.z);
                    acc.w = fmaf(a.x, w0.w, acc.w);
                    acc.x = fmaf(a.y, w1.x, acc.x);
                    acc.y = fmaf(a.y, w1.y, acc.y);
                    acc.z = fmaf(a.y, w1.z, acc.z);
                    acc.w = fmaf(a.y, w1.w, acc.w);
                    acc.x = fmaf(a.z, w2.x, acc.x);
                    acc.y = fmaf(a.z, w2.y, acc.y);
                    acc.z = fmaf(a.z, w2.z, acc.z);
                    acc.w = fmaf(a.z, w2.w, acc.w);
                    acc.x = fmaf(a.w, w3.x, acc.x);
                    acc.y = fmaf(a.w, w3.y, acc.y);
                    acc.z = fmaf(a.w, w3.z, acc.z);
                    acc.w = fmaf(a.w, w3.w, acc.w);
                }
            }
        }

        // new = cur + relu(conv). cur is read/written only by this thread.
        const size_t ob = baseb + (size_t)tgt * RS + (size_t)w * TS + c0;
        float4 cur = __ldcg((const float4*)(g_Y + ob));
        float4 o;
        o.x = cur.x + fmaxf(acc.x, 0.f);
        o.y = cur.y + fmaxf(acc.y, 0.f);
        o.z = cur.z + fmaxf(acc.z, 0.f);
        o.w = cur.w + fmaxf(acc.w, 0.f);
        __stcg((float4*)(g_Y + ob), o);

        __threadfence();
        __syncthreads();
        if (tid == 0) atomicAdd(cnt + s, 1);
    }
}

extern "C" void kernel_launch(void* const* d_in, const int* in_sizes, int n_in,
                              void* d_out, int out_size) {
    const float* x   = (const float*)d_in[0];
    const float* ktd = (const float*)d_in[1];
    const float* kdt = (const float*)d_in[2];
    const float* klr = (const float*)d_in[3];
    const float* krl = (const float*)d_in[4];
    float* out = (float*)d_out;

    const size_t smem = (size_t)(KWN * CN * COS + WN * ROWP) * sizeof(float); // 104448
    cudaFuncSetAttribute(scan_k, cudaFuncAttributeMaxDynamicSharedMemorySize, (int)smem);

    float* Yp = nullptr;
    cudaGetSymbolAddress((void**)&Yp, g_Y);

    zero_cnt_k<<<(4 * BN * HN + 255) / 256, 256>>>();

    // NCHW -> NHWC: per batch transpose (128 x 16384) -> (16384 x 128)
    transpose_k<<<dim3(16384 / 32, 128 / 32, BN), dim3(32, 8)>>>(x, Yp, 128, 16384);

    dim3 sgrid(GSL, BN);
    // TD: scan over H (row stride W*C), conv over W (stride C)
    scan_k<<<sgrid, NTH, smem>>>(ktd, 0, WN * CN, CN, 0);
    // DT: same geometry, reversed
    scan_k<<<sgrid, NTH, smem>>>(kdt, 1, WN * CN, CN, 1);
    // LR: scan over W (row stride C), conv over H (stride W*C)
    scan_k<<<sgrid, NTH, smem>>>(klr, 2, CN, WN * CN, 0);
    // RL: same geometry, reversed
    scan_k<<<sgrid, NTH, smem>>>(krl, 3, CN, WN * CN, 1);

    // NHWC -> NCHW
    transpose_k<<<dim3(128 / 32, 16384 / 32, BN), dim3(32, 8)>>>(Yp, out, 16384, 128);
}

// round 8
// speedup vs baseline: 1.0568x; 1.0568x over previous
#include <cuda_runtime.h>

#define BN 8
#define CN 128
#define HN 128
#define WN 128
#define KWN 9
#define PWN 4
#define GSL 16          // CTAs per batch (co-slices)
#define COS 8           // output channels per CTA
#define NTH 256
#define ROWP 132        // padded smem row pitch (floats) -> conflict-free
#define BSTR (HN*WN*CN) // per-batch stride in floats

typedef unsigned long long ull;

// Packed f32x2 FMA: acc.{lo,hi} += a.{lo,hi} * b.{lo,hi}
#define FMA2(acc, a, b) \
    asm("fma.rn.f32x2 %0, %1, %2, %0;" : "+l"(acc) : "l"(a), "l"(b))

__device__ __forceinline__ float hadd2(ull v) {
    float lo, hi;
    asm("mov.b64 {%0, %1}, %2;" : "=f"(lo), "=f"(hi) : "l"(v));
    return lo + hi;
}

// Scratch state tensor in NHWC, processed in-place by all 4 scans.
__device__ float g_Y[(size_t)BN * HN * WN * CN];
// Per-phase, per-batch, per-step completion counters.
__device__ int g_cnt[4 * BN * HN];

__global__ void zero_cnt_k() {
    int i = blockIdx.x * blockDim.x + threadIdx.x;
    if (i < 4 * BN * HN) g_cnt[i] = 0;
}

// Generic per-batch tiled transpose: in is (B, R, Cc), out is (B, Cc, R).
__global__ void transpose_k(const float* __restrict__ in, float* __restrict__ out,
                            int R, int Cc) {
    __shared__ float tile[32][33];
    int b = blockIdx.z;
    size_t base = (size_t)b * R * Cc;
    int j0 = blockIdx.x << 5, i0 = blockIdx.y << 5;
    int tx = threadIdx.x, ty = threadIdx.y;
#pragma unroll
    for (int k = 0; k < 32; k += 8)
        tile[ty + k][tx] = in[base + (size_t)(i0 + ty + k) * Cc + (j0 + tx)];
    __syncthreads();
#pragma unroll
    for (int k = 0; k < 32; k += 8)
        out[base + (size_t)(j0 + ty + k) * R + (i0 + tx)] = tile[tx][ty + k];
}

// One directional scan, persistent. Grid (GSL, BN), 256 threads.
// Recurrence: Y[tgt] = Y[tgt] + relu(conv_KW9(Y[src]))   (in-place, NHWC scratch).
// Inner product runs on packed fma.rn.f32x2: partial sums packed over ci-parity,
// weights stored transposed [kk][co][ci] so both operands are natural 64-bit pairs.
__global__ void __launch_bounds__(NTH, 1)
scan_k(const float* __restrict__ kern, int phase, int RS, int TS, int rev) {
    extern __shared__ float sm[];
    float* ws = sm;                  // [KWN][COS][CN] transposed weight slice: 9216 floats
    float* ps = sm + KWN * CN * COS; // [WN][ROWP] staged prev row

    const int tid = threadIdx.x;
    const int b = blockIdx.y, g = blockIdx.x;
    const int co0 = g * COS;

    // Load this CTA's weight slice once, TRANSPOSED to [kk][j][ci].
    for (int i = tid; i < KWN * COS * CN; i += NTH) {
        int kwi = i / (COS * CN);
        int r = i - kwi * (COS * CN);
        int j = r / CN, ci = r - j * CN;
        ws[i] = kern[(kwi * CN + ci) * CN + co0 + j];
    }
    __syncthreads();

    const int lane = tid & 31, wq = tid >> 5;
    const int w = (wq << 4) + (lane & 15);  // conv-axis position this lane owns
    const int ch = lane >> 4;               // which half of the 8 co's
    const int coL = ch << 2;                // local co base (0 or 4)
    const int c0 = co0 + coL;
    const size_t baseb = (size_t)b * BSTR;
    int* cnt = g_cnt + (phase * BN + b) * HN;

    for (int s = 1; s < HN; s++) {
        const int tgt = rev ? (HN - 1 - s) : s;
        const int src = rev ? (tgt + 1) : (tgt - 1);

        // Wait until all GSL CTAs of this batch finished step s-1.
        if (s > 1) {
            if (tid == 0) {
                volatile int* p = cnt + (s - 1);
                while (*p < GSL) __nanosleep(64);
            }
            __syncthreads();
        }

        // Stage src row (128 positions x 128 channels) into padded smem.
        {
            const size_t rb = baseb + (size_t)src * RS;
            for (int i = tid; i < WN * (CN / 4); i += NTH) {
                int t = i >> 5;
                int cq = (i & 31) << 2;
                float4 v = __ldcg((const float4*)(g_Y + rb + (size_t)t * TS + cq));
                *(float4*)(ps + t * ROWP + cq) = v;
            }
        }
        __syncthreads();

        // Prefetch target-row current value (this thread's exclusive 4 floats).
        const size_t ob = baseb + (size_t)tgt * RS + (size_t)w * TS + c0;
        float4 cur = __ldcg((const float4*)(g_Y + ob));

        // conv: out[j] = sum_{kk,ci} prev[w+kk-4, ci] * K[kk, ci, c0+j]
        // acc_j packed over ci parity: {even partial, odd partial}.
        ull acc0 = 0ull, acc1 = 0ull, acc2 = 0ull, acc3 = 0ull;
#pragma unroll
        for (int kk = 0; kk < KWN; kk++) {
            const int wr = w + kk - PWN;
            if ((unsigned)wr < (unsigned)WN) {
                const float* pr = ps + wr * ROWP;
                const float* wb0 = ws + (kk * COS + coL) * CN;
#pragma unroll 8
                for (int ci = 0; ci < CN; ci += 4) {
                    ulonglong2 a = *(const ulonglong2*)(pr + ci);
                    ulonglong2 w0 = *(const ulonglong2*)(wb0 + ci);
                    ulonglong2 w1 = *(const ulonglong2*)(wb0 + CN + ci);
                    ulonglong2 w2 = *(const ulonglong2*)(wb0 + 2 * CN + ci);
                    ulonglong2 w3 = *(const ulonglong2*)(wb0 + 3 * CN + ci);
                    FMA2(acc0, a.x, w0.x); FMA2(acc0, a.y, w0.y);
                    FMA2(acc1, a.x, w1.x); FMA2(acc1, a.y, w1.y);
                    FMA2(acc2, a.x, w2.x); FMA2(acc2, a.y, w2.y);
                    FMA2(acc3, a.x, w3.x); FMA2(acc3, a.y, w3.y);
                }
            }
        }

        // new = cur + relu(conv). cur is read/written only by this thread.
        float4 o;
        o.x = cur.x + fmaxf(hadd2(acc0), 0.f);
        o.y = cur.y + fmaxf(hadd2(acc1), 0.f);
        o.z = cur.z + fmaxf(hadd2(acc2), 0.f);
        o.w = cur.w + fmaxf(hadd2(acc3), 0.f);
        __stcg((float4*)(g_Y + ob), o);

        __threadfence();
        __syncthreads();
        if (tid == 0) atomicAdd(cnt + s, 1);
    }
}

extern "C" void kernel_launch(void* const* d_in, const int* in_sizes, int n_in,
                              void* d_out, int out_size) {
    const float* x   = (const float*)d_in[0];
    const float* ktd = (const float*)d_in[1];
    const float* kdt = (const float*)d_in[2];
    const float* klr = (const float*)d_in[3];
    const float* krl = (const float*)d_in[4];
    float* out = (float*)d_out;

    const size_t smem = (size_t)(KWN * CN * COS + WN * ROWP) * sizeof(float); // 104448
    cudaFuncSetAttribute(scan_k, cudaFuncAttributeMaxDynamicSharedMemorySize, (int)smem);

    float* Yp = nullptr;
    cudaGetSymbolAddress((void**)&Yp, g_Y);

    zero_cnt_k<<<(4 * BN * HN + 255) / 256, 256>>>();

    // NCHW -> NHWC: per batch transpose (128 x 16384) -> (16384 x 128)
    transpose_k<<<dim3(16384 / 32, 128 / 32, BN), dim3(32, 8)>>>(x, Yp, 128, 16384);

    dim3 sgrid(GSL, BN);
    // TD: scan over H (row stride W*C), conv over W (stride C)
    scan_k<<<sgrid, NTH, smem>>>(ktd, 0, WN * CN, CN, 0);
    // DT: same geometry, reversed
    scan_k<<<sgrid, NTH, smem>>>(kdt, 1, WN * CN, CN, 1);
    // LR: scan over W (row stride C), conv over H (stride W*C)
    scan_k<<<sgrid, NTH, smem>>>(klr, 2, CN, WN * CN, 0);
    // RL: same geometry, reversed
    scan_k<<<sgrid, NTH, smem>>>(krl, 3, CN, WN * CN, 1);

    // NHWC -> NCHW
    transpose_k<<<dim3(128 / 32, 16384 / 32, BN), dim3(32, 8)>>>(Yp, out, 16384, 128);
}